// round 4
// baseline (speedup 1.0000x reference)
#include <cuda_runtime.h>
#include <cstdint>

// ============================================================
// TemporalSelfAttentionClusterKey  (B=8,T=192,N=64,D=512,H=8,DH=64,C=8)
//   Q = x @ Wq^T + bq ; V = x @ Wv^T + bv ; K = x @ Wk[cid[n]] + bk[cid[n]]
//   per (b,n,h): S = Q K^T / 8 ; P = softmax(S) ; O = P V
//   out = O @ proj^T + bproj
// tf32 mma.sync (m16n8k8), fp32 accumulate. GEMM kernels use cp.async
// double-buffered tiles (raw f32 in smem, RNA-round to tf32 at fragment
// load). Q/K/V/O scratch is stored pre-rounded for the attention kernel.
// ============================================================

#define TT   192
#define DD   512
#define NN   64
#define DH   64

static const size_t TOK_PER_BN = (size_t)TT * DD;      // 98304 floats per (b,n)

__device__ float g_Q[50331648];
__device__ float g_K[50331648];
__device__ float g_V[50331648];
__device__ float g_O[50331648];
__device__ int   g_cid[64];

__device__ __forceinline__ float f2tf(float x) {
    unsigned r;
    asm("cvt.rna.tf32.f32 %0, %1;" : "=r"(r) : "f"(x));
    return __uint_as_float(r);
}
__device__ __forceinline__ unsigned f2tfu(float x) {
    unsigned r;
    asm("cvt.rna.tf32.f32 %0, %1;" : "=r"(r) : "f"(x));
    return r;
}

__device__ __forceinline__ void mma_tf32(float* d, const unsigned* a, const unsigned* b) {
    asm volatile(
        "mma.sync.aligned.m16n8k8.row.col.f32.tf32.tf32.f32 "
        "{%0,%1,%2,%3}, {%4,%5,%6,%7}, {%8,%9}, {%0,%1,%2,%3};\n"
        : "+f"(d[0]), "+f"(d[1]), "+f"(d[2]), "+f"(d[3])
        : "r"(a[0]), "r"(a[1]), "r"(a[2]), "r"(a[3]), "r"(b[0]), "r"(b[1]));
}

__device__ __forceinline__ void cp_async16(void* smem_dst, const void* gmem_src) {
    unsigned s = (unsigned)__cvta_generic_to_shared(smem_dst);
    asm volatile("cp.async.cg.shared.global [%0], [%1], 16;\n" :: "r"(s), "l"(gmem_src));
}
#define CP_COMMIT() asm volatile("cp.async.commit_group;\n")
#define CP_WAIT1()  asm volatile("cp.async.wait_group 1;\n")
#define CP_WAIT0()  asm volatile("cp.async.wait_group 0;\n")

#define U(x) __float_as_uint(x)

// ------------------------------------------------------------
// Kernel 0: decode cluster_ids robustly (int64 vs int32 on disk).
// int64-LE with values 0..7 has words 1,3,...,63 all zero.
// ------------------------------------------------------------
__global__ void decode_cid_kernel(const int* __restrict__ p)
{
    __shared__ int is64;
    if (threadIdx.x == 0) {
        int all0 = 1;
        for (int i = 1; i < 64; i += 2) all0 &= (p[i] == 0);
        is64 = all0;
    }
    __syncthreads();
    int n = threadIdx.x;           // 64 threads
    g_cid[n] = is64 ? p[2 * n] : p[n];
}

// ------------------------------------------------------------
// Kernel 1: fused Q/V/K projection, BN=256, cp.async double-buffered.
// grid = (6 col-tiles of 256, 3 t-tiles of 64, 512 bn), 256 threads.
// col tiles 0..1 -> Q, 2..3 -> V (B[n][k] = W rows), 4..5 -> K (B[k][n]).
// warp tile 32x64: acc[2][8][4].
// ------------------------------------------------------------
#define A_STRIDE  36          // 36%32==4 : A frag gathers conflict-free
#define A_STAGE   (64 * A_STRIDE)          // 2304 floats
#define BN_STRIDE 36          // n-major B view
#define BS_STRIDE 264         // k-major B view (K region): 264%32==8
#define B_STAGE   (256 * BN_STRIDE)        // 9216 floats (>= 32*264=8448)
#define GEMM_SMEM_FLOATS (2 * A_STAGE + 2 * B_STAGE)
#define GEMM_SMEM_BYTES  (GEMM_SMEM_FLOATS * 4)       // 92160 B

__global__ __launch_bounds__(256) void qkv_kernel(
    const float* __restrict__ x,
    const float* __restrict__ Wq, const float* __restrict__ bq,
    const float* __restrict__ Wv, const float* __restrict__ bv,
    const float* __restrict__ Wk, const float* __restrict__ bk)
{
    extern __shared__ float dsm[];
    float* Abase = dsm;                     // 2 stages of [64][36]
    float* Bbase = dsm + 2 * A_STAGE;       // 2 stages of 9216

    const int bn = blockIdx.z;
    const int b  = bn >> 6;
    const int n  = bn & 63;
    const int t0 = blockIdx.y * 64;
    const int j0 = blockIdx.x * 256;
    const int tid  = threadIdx.x;
    const int lane = tid & 31;
    const int warp = tid >> 5;
    const int wm = warp & 1;        // 2 row groups of 32
    const int wn = warp >> 1;       // 4 col groups of 64

    const int region = j0 >> 9;     // 0=Q 1=V 2=K
    const int jloc   = j0 & 511;    // 0 or 256
    const float* W;
    const float* bias;
    if (region == 0)      { W = Wq; bias = bq; }
    else if (region == 1) { W = Wv; bias = bv; }
    else {
        int c = g_cid[n];
        W = Wk + (size_t)c * DD * DD;
        bias = bk + (size_t)c * DD;
    }

    const float* xrow = x + ((size_t)((b * TT + t0) * NN + n)) * DD;

    float acc[2][8][4];
#pragma unroll
    for (int i = 0; i < 2; i++)
#pragma unroll
        for (int j = 0; j < 8; j++)
#pragma unroll
            for (int k = 0; k < 4; k++) acc[i][j][k] = 0.f;

    // ---- async tile issue for (k0, stage)
    auto issue = [&](int k0, int st) {
        float* A = Abase + st * A_STAGE;
        float* Bt = Bbase + st * B_STAGE;
#pragma unroll
        for (int i = 0; i < 2; i++) {
            int id = tid + i * 256;
            int r  = id >> 3;
            int c4 = (id & 7) * 4;
            cp_async16(A + r * A_STRIDE + c4,
                       xrow + (size_t)r * NN * DD + k0 + c4);
        }
        if (region < 2) {
#pragma unroll
            for (int i = 0; i < 8; i++) {
                int id = tid + i * 256;
                int nn = id >> 3;
                int k4 = (id & 7) * 4;
                cp_async16(Bt + nn * BN_STRIDE + k4,
                           W + (size_t)(jloc + nn) * DD + k0 + k4);
            }
        } else {
#pragma unroll
            for (int i = 0; i < 8; i++) {
                int id = tid + i * 256;
                int kk = id >> 6;
                int c4 = (id & 63) * 4;
                cp_async16(Bt + kk * BS_STRIDE + c4,
                           W + (size_t)(k0 + kk) * DD + jloc + c4);
            }
        }
        CP_COMMIT();
    };

    issue(0, 0);

    for (int it = 0; it < 16; it++) {
        if (it < 15) issue((it + 1) * 32, (it + 1) & 1);
        if (it < 15) CP_WAIT1(); else CP_WAIT0();
        __syncthreads();

        const float (*As)[A_STRIDE] = (const float(*)[A_STRIDE])(Abase + (it & 1) * A_STAGE);
        const float* Bt = Bbase + (it & 1) * B_STAGE;
        const float (*Bn)[BN_STRIDE] = (const float(*)[BN_STRIDE])Bt;
        const float (*Bs)[BS_STRIDE] = (const float(*)[BS_STRIDE])Bt;

#pragma unroll
        for (int kk = 0; kk < 32; kk += 8) {
            unsigned a[2][4], bf[8][2];
#pragma unroll
            for (int mi = 0; mi < 2; mi++) {
                int r = wm * 32 + mi * 16 + (lane >> 2);
                int c = kk + (lane & 3);
                a[mi][0] = f2tfu(As[r][c]);
                a[mi][1] = f2tfu(As[r + 8][c]);
                a[mi][2] = f2tfu(As[r][c + 4]);
                a[mi][3] = f2tfu(As[r + 8][c + 4]);
            }
            if (region < 2) {
#pragma unroll
                for (int ni = 0; ni < 8; ni++) {
                    int nc = wn * 64 + ni * 8 + (lane >> 2);
                    int kr = kk + (lane & 3);
                    bf[ni][0] = f2tfu(Bn[nc][kr]);
                    bf[ni][1] = f2tfu(Bn[nc][kr + 4]);
                }
            } else {
#pragma unroll
                for (int ni = 0; ni < 8; ni++) {
                    int nc = wn * 64 + ni * 8 + (lane >> 2);
                    int kr = kk + (lane & 3);
                    bf[ni][0] = f2tfu(Bs[kr][nc]);
                    bf[ni][1] = f2tfu(Bs[kr + 4][nc]);
                }
            }
#pragma unroll
            for (int mi = 0; mi < 2; mi++)
#pragma unroll
                for (int ni = 0; ni < 8; ni++)
                    mma_tf32(acc[mi][ni], a[mi], bf[ni]);
        }
        __syncthreads();
    }

    // epilogue: add bias, round to tf32 (attn consumes as mma operands).
    float* dst = (region == 0) ? g_Q : ((region == 1) ? g_V : g_K);
    const size_t base = (size_t)bn * TOK_PER_BN;
#pragma unroll
    for (int mi = 0; mi < 2; mi++) {
#pragma unroll
        for (int ni = 0; ni < 8; ni++) {
            int r = t0 + wm * 32 + mi * 16 + (lane >> 2);
            int c = jloc + wn * 64 + ni * 8 + 2 * (lane & 3);
            float b0 = bias[c], b1 = bias[c + 1];
            dst[base + (size_t)r * DD + c]           = f2tf(acc[mi][ni][0] + b0);
            dst[base + (size_t)r * DD + c + 1]       = f2tf(acc[mi][ni][1] + b1);
            dst[base + (size_t)(r + 8) * DD + c]     = f2tf(acc[mi][ni][2] + b0);
            dst[base + (size_t)(r + 8) * DD + c + 1] = f2tf(acc[mi][ni][3] + b1);
        }
    }
}

// ------------------------------------------------------------
// Kernel 2: attention per (b,n,h), q-tile of 64 rows.
// grid = (3 q-tiles, 8 heads, 512 bn), 256 threads, ~171KB dyn smem.
// ------------------------------------------------------------
#define KS_STRIDE 68     // K & Q tiles  (68%32==4 : frag gathers conflict-free)
#define VS_STRIDE 72     // V tile       (72%32==8 : phase-3 B gathers conflict-free)
#define SS_STRIDE 196
#define ATTN_SMEM_FLOATS (192 * KS_STRIDE + 192 * VS_STRIDE + 64 * KS_STRIDE + 64 * SS_STRIDE)
#define ATTN_SMEM_BYTES  (ATTN_SMEM_FLOATS * 4)

__global__ __launch_bounds__(256) void attn_kernel()
{
    extern __shared__ float sm[];
    float (*Ks)[KS_STRIDE] = (float(*)[KS_STRIDE])sm;
    float (*Vs)[VS_STRIDE] = (float(*)[VS_STRIDE])(sm + 192 * KS_STRIDE);
    float (*Qs)[KS_STRIDE] = (float(*)[KS_STRIDE])(sm + 192 * KS_STRIDE + 192 * VS_STRIDE);
    float (*Ss)[SS_STRIDE] = (float(*)[SS_STRIDE])(sm + 192 * KS_STRIDE + 192 * VS_STRIDE + 64 * KS_STRIDE);

    const int bn  = blockIdx.z;
    const int h   = blockIdx.y;
    const int tq0 = blockIdx.x * 64;
    const int tid  = threadIdx.x;
    const int lane = tid & 31;
    const int warp = tid >> 5;
    const int wm = warp & 1;
    const int wn = warp >> 1;

    const size_t base = (size_t)bn * TOK_PER_BN + (size_t)h * DH;

    // ---- loads: K,V full [192,64]; Q tile [64,64]. Already tf32-rounded.
#pragma unroll
    for (int i = 0; i < 12; i++) {
        int id = tid + i * 256;
        int r  = id >> 4;
        int c4 = (id & 15) * 4;
        *(float4*)&Ks[r][c4] = *(const float4*)(g_K + base + (size_t)r * DD + c4);
        *(float4*)&Vs[r][c4] = *(const float4*)(g_V + base + (size_t)r * DD + c4);
    }
#pragma unroll
    for (int i = 0; i < 4; i++) {
        int id = tid + i * 256;
        int r  = id >> 4;
        int c4 = (id & 15) * 4;
        *(float4*)&Qs[r][c4] = *(const float4*)(g_Q + base + (size_t)(tq0 + r) * DD + c4);
    }
    __syncthreads();

    // ---- phase 1: S = Q K^T  (64x192, k=64); warp tile 32x48
    {
        float acc[2][6][4];
#pragma unroll
        for (int i = 0; i < 2; i++)
#pragma unroll
            for (int j = 0; j < 6; j++)
#pragma unroll
                for (int k = 0; k < 4; k++) acc[i][j][k] = 0.f;

#pragma unroll
        for (int kk = 0; kk < DH; kk += 8) {
            unsigned a[2][4], bf[6][2];
#pragma unroll
            for (int mi = 0; mi < 2; mi++) {
                int r = wm * 32 + mi * 16 + (lane >> 2);
                int c = kk + (lane & 3);
                a[mi][0] = U(Qs[r][c]);
                a[mi][1] = U(Qs[r + 8][c]);
                a[mi][2] = U(Qs[r][c + 4]);
                a[mi][3] = U(Qs[r + 8][c + 4]);
            }
#pragma unroll
            for (int ni = 0; ni < 6; ni++) {
                int nc = wn * 48 + ni * 8 + (lane >> 2);
                int kr = kk + (lane & 3);
                bf[ni][0] = U(Ks[nc][kr]);       // B[k][n] = K[n][k]
                bf[ni][1] = U(Ks[nc][kr + 4]);
            }
#pragma unroll
            for (int mi = 0; mi < 2; mi++)
#pragma unroll
                for (int ni = 0; ni < 6; ni++)
                    mma_tf32(acc[mi][ni], a[mi], bf[ni]);
        }
#pragma unroll
        for (int mi = 0; mi < 2; mi++) {
#pragma unroll
            for (int ni = 0; ni < 6; ni++) {
                int r = wm * 32 + mi * 16 + (lane >> 2);
                int c = wn * 48 + ni * 8 + 2 * (lane & 3);
                Ss[r][c]         = acc[mi][ni][0] * 0.125f;
                Ss[r][c + 1]     = acc[mi][ni][1] * 0.125f;
                Ss[r + 8][c]     = acc[mi][ni][2] * 0.125f;
                Ss[r + 8][c + 1] = acc[mi][ni][3] * 0.125f;
            }
        }
    }
    __syncthreads();

    // ---- phase 2: softmax, 4 threads per row; store P rounded to tf32.
    {
        const int r = tid >> 2;
        const int g = tid & 3;
        float m = -1e30f;
        for (int c = g; c < 192; c += 4) m = fmaxf(m, Ss[r][c]);
        m = fmaxf(m, __shfl_xor_sync(0xFFFFFFFFu, m, 1));
        m = fmaxf(m, __shfl_xor_sync(0xFFFFFFFFu, m, 2));
        float s = 0.f;
        for (int c = g; c < 192; c += 4) {
            float e = __expf(Ss[r][c] - m);
            Ss[r][c] = e;
            s += e;
        }
        s += __shfl_xor_sync(0xFFFFFFFFu, s, 1);
        s += __shfl_xor_sync(0xFFFFFFFFu, s, 2);
        float inv = 1.0f / s;
        for (int c = g; c < 192; c += 4) Ss[r][c] = f2tf(Ss[r][c] * inv);
    }
    __syncthreads();

    // ---- phase 3: O = P V (64x64, k=192); warp tile 32x16
    {
        float acc[2][2][4];
#pragma unroll
        for (int i = 0; i < 2; i++)
#pragma unroll
            for (int j = 0; j < 2; j++)
#pragma unroll
                for (int k = 0; k < 4; k++) acc[i][j][k] = 0.f;

#pragma unroll
        for (int kk = 0; kk < 192; kk += 8) {
            unsigned a[2][4], bf[2][2];
#pragma unroll
            for (int mi = 0; mi < 2; mi++) {
                int r = wm * 32 + mi * 16 + (lane >> 2);
                int c = kk + (lane & 3);
                a[mi][0] = U(Ss[r][c]);
                a[mi][1] = U(Ss[r + 8][c]);
                a[mi][2] = U(Ss[r][c + 4]);
                a[mi][3] = U(Ss[r + 8][c + 4]);
            }
#pragma unroll
            for (int ni = 0; ni < 2; ni++) {
                int nc = wn * 16 + ni * 8 + (lane >> 2);
                int kr = kk + (lane & 3);
                bf[ni][0] = U(Vs[kr][nc]);
                bf[ni][1] = U(Vs[kr + 4][nc]);
            }
#pragma unroll
            for (int mi = 0; mi < 2; mi++)
#pragma unroll
                for (int ni = 0; ni < 2; ni++)
                    mma_tf32(acc[mi][ni], a[mi], bf[ni]);
        }

#pragma unroll
        for (int mi = 0; mi < 2; mi++) {
#pragma unroll
            for (int ni = 0; ni < 2; ni++) {
                int r = wm * 32 + mi * 16 + (lane >> 2);
                int c = wn * 16 + ni * 8 + 2 * (lane & 3);
                size_t o0 = (size_t)bn * TOK_PER_BN + (size_t)(tq0 + r) * DD + h * DH + c;
                size_t o8 = (size_t)bn * TOK_PER_BN + (size_t)(tq0 + r + 8) * DD + h * DH + c;
                g_O[o0]     = f2tf(acc[mi][ni][0]);
                g_O[o0 + 1] = f2tf(acc[mi][ni][1]);
                g_O[o8]     = f2tf(acc[mi][ni][2]);
                g_O[o8 + 1] = f2tf(acc[mi][ni][3]);
            }
        }
    }
}

// ------------------------------------------------------------
// Kernel 3: output projection, BN=256, cp.async double-buffered.
// out[b,t,n,e] = sum_d O[bn,t,d] * P[e,d] + pb[e]
// grid = (2 col-tiles of 256, 3 t-tiles, 512 bn), 256 threads.
// ------------------------------------------------------------
__global__ __launch_bounds__(256) void proj_kernel(
    const float* __restrict__ Pw, const float* __restrict__ Pb,
    float* __restrict__ out)
{
    extern __shared__ float dsm[];
    float* Abase = dsm;
    float* Bbase = dsm + 2 * A_STAGE;

    const int bn = blockIdx.z;
    const int b  = bn >> 6;
    const int n  = bn & 63;
    const int t0 = blockIdx.y * 64;
    const int j0 = blockIdx.x * 256;
    const int tid  = threadIdx.x;
    const int lane = tid & 31;
    const int warp = tid >> 5;
    const int wm = warp & 1;
    const int wn = warp >> 1;

    const float* A = g_O + (size_t)bn * TOK_PER_BN + (size_t)t0 * DD;

    float acc[2][8][4];
#pragma unroll
    for (int i = 0; i < 2; i++)
#pragma unroll
        for (int j = 0; j < 8; j++)
#pragma unroll
            for (int k = 0; k < 4; k++) acc[i][j][k] = 0.f;

    auto issue = [&](int k0, int st) {
        float* Asm = Abase + st * A_STAGE;
        float* Bt  = Bbase + st * B_STAGE;
#pragma unroll
        for (int i = 0; i < 2; i++) {
            int id = tid + i * 256;
            int r  = id >> 3;
            int c4 = (id & 7) * 4;
            cp_async16(Asm + r * A_STRIDE + c4, A + (size_t)r * DD + k0 + c4);
        }
#pragma unroll
        for (int i = 0; i < 8; i++) {
            int id = tid + i * 256;
            int nn = id >> 3;
            int k4 = (id & 7) * 4;
            cp_async16(Bt + nn * BN_STRIDE + k4,
                       Pw + (size_t)(j0 + nn) * DD + k0 + k4);
        }
        CP_COMMIT();
    };

    issue(0, 0);

    for (int it = 0; it < 16; it++) {
        if (it < 15) issue((it + 1) * 32, (it + 1) & 1);
        if (it < 15) CP_WAIT1(); else CP_WAIT0();
        __syncthreads();

        const float (*As)[A_STRIDE] = (const float(*)[A_STRIDE])(Abase + (it & 1) * A_STAGE);
        const float (*Bn)[BN_STRIDE] = (const float(*)[BN_STRIDE])(Bbase + (it & 1) * B_STAGE);

#pragma unroll
        for (int kk = 0; kk < 32; kk += 8) {
            unsigned a[2][4], bf[8][2];
#pragma unroll
            for (int mi = 0; mi < 2; mi++) {
                int r = wm * 32 + mi * 16 + (lane >> 2);
                int c = kk + (lane & 3);
                a[mi][0] = f2tfu(As[r][c]);
                a[mi][1] = f2tfu(As[r + 8][c]);
                a[mi][2] = f2tfu(As[r][c + 4]);
                a[mi][3] = f2tfu(As[r + 8][c + 4]);
            }
#pragma unroll
            for (int ni = 0; ni < 8; ni++) {
                int nc = wn * 64 + ni * 8 + (lane >> 2);
                int kr = kk + (lane & 3);
                bf[ni][0] = f2tfu(Bn[nc][kr]);
                bf[ni][1] = f2tfu(Bn[nc][kr + 4]);
            }
#pragma unroll
            for (int mi = 0; mi < 2; mi++)
#pragma unroll
                for (int ni = 0; ni < 8; ni++)
                    mma_tf32(acc[mi][ni], a[mi], bf[ni]);
        }
        __syncthreads();
    }

#pragma unroll
    for (int mi = 0; mi < 2; mi++) {
#pragma unroll
        for (int ni = 0; ni < 8; ni++) {
            int r = t0 + wm * 32 + mi * 16 + (lane >> 2);
            int c = j0 + wn * 64 + ni * 8 + 2 * (lane & 3);
            float b0 = Pb[c], b1 = Pb[c + 1];
            size_t o0 = ((size_t)(b * TT + r) * NN + n) * DD + c;
            size_t o8 = ((size_t)(b * TT + r + 8) * NN + n) * DD + c;
            out[o0]     = acc[mi][ni][0] + b0;
            out[o0 + 1] = acc[mi][ni][1] + b1;
            out[o8]     = acc[mi][ni][2] + b0;
            out[o8 + 1] = acc[mi][ni][3] + b1;
        }
    }
}

// ------------------------------------------------------------
extern "C" void kernel_launch(void* const* d_in, const int* in_sizes, int n_in,
                              void* d_out, int out_size)
{
    const float* x      = (const float*)d_in[0];
    const float* Wq_w   = (const float*)d_in[1];
    const float* Wq_b   = (const float*)d_in[2];
    const float* Wv_w   = (const float*)d_in[3];
    const float* Wv_b   = (const float*)d_in[4];
    const float* Wk     = (const float*)d_in[5];
    const float* bk     = (const float*)d_in[6];
    const float* proj_w = (const float*)d_in[7];
    const float* proj_b = (const float*)d_in[8];
    const int*   cid    = (const int*)d_in[9];     // int32 or int64 — decoded on device
    float* out = (float*)d_out;

    cudaFuncSetAttribute(qkv_kernel,  cudaFuncAttributeMaxDynamicSharedMemorySize, GEMM_SMEM_BYTES);
    cudaFuncSetAttribute(proj_kernel, cudaFuncAttributeMaxDynamicSharedMemorySize, GEMM_SMEM_BYTES);
    cudaFuncSetAttribute(attn_kernel, cudaFuncAttributeMaxDynamicSharedMemorySize, ATTN_SMEM_BYTES);

    decode_cid_kernel<<<1, 64>>>(cid);

    dim3 g1(6, 3, 512);
    qkv_kernel<<<g1, 256, GEMM_SMEM_BYTES>>>(x, Wq_w, Wq_b, Wv_w, Wv_b, Wk, bk);

    dim3 g2(3, 8, 512);
    attn_kernel<<<g2, 256, ATTN_SMEM_BYTES>>>();

    dim3 g3(2, 3, 512);
    proj_kernel<<<g3, 256, GEMM_SMEM_BYTES>>>(proj_w, proj_b, out);
}

// round 5
// speedup vs baseline: 1.0482x; 1.0482x over previous
#include <cuda_runtime.h>
#include <cstdint>

// ============================================================
// TemporalSelfAttentionClusterKey  (B=8,T=192,N=64,D=512,H=8,DH=64,C=8)
//   Q = x @ Wq^T + bq ; V = x @ Wv^T + bv ; K = x @ Wk[cid[n]] + bk[cid[n]]
//   per (b,n,h): S = Q K^T / 8 ; P = softmax(S) ; O = P V
//   out = O @ proj^T + bproj
// tf32 mma.sync (m16n8k8), fp32 accumulate. Weights pre-rounded to tf32
// in scratch (kills B-fragment cvts); g_Q/g_K/g_V/g_O stored pre-rounded
// (kills A-fragment cvts in proj and all cvts in attn).
// ============================================================

#define TT   192
#define DD   512
#define NN   64
#define DH   64

static const size_t TOK_PER_BN = (size_t)TT * DD;      // 98304 floats per (b,n)

__device__ float g_Q[50331648];
__device__ float g_K[50331648];
__device__ float g_V[50331648];
__device__ float g_O[50331648];
__device__ int   g_cid[64];
// tf32-pre-rounded weights
__device__ float g_Wqr[262144];
__device__ float g_Wvr[262144];
__device__ float g_Pwr[262144];
__device__ float g_Wkr[2097152];

__device__ __forceinline__ float f2tf(float x) {
    unsigned r;
    asm("cvt.rna.tf32.f32 %0, %1;" : "=r"(r) : "f"(x));
    return __uint_as_float(r);
}
__device__ __forceinline__ unsigned f2tfu(float x) {
    unsigned r;
    asm("cvt.rna.tf32.f32 %0, %1;" : "=r"(r) : "f"(x));
    return r;
}

__device__ __forceinline__ void mma_tf32(float* d, const unsigned* a, const unsigned* b) {
    asm volatile(
        "mma.sync.aligned.m16n8k8.row.col.f32.tf32.tf32.f32 "
        "{%0,%1,%2,%3}, {%4,%5,%6,%7}, {%8,%9}, {%0,%1,%2,%3};\n"
        : "+f"(d[0]), "+f"(d[1]), "+f"(d[2]), "+f"(d[3])
        : "r"(a[0]), "r"(a[1]), "r"(a[2]), "r"(a[3]), "r"(b[0]), "r"(b[1]));
}

__device__ __forceinline__ void cp_async16(void* smem_dst, const void* gmem_src) {
    unsigned s = (unsigned)__cvta_generic_to_shared(smem_dst);
    asm volatile("cp.async.cg.shared.global [%0], [%1], 16;\n" :: "r"(s), "l"(gmem_src));
}
#define CP_COMMIT() asm volatile("cp.async.commit_group;\n")
#define CP_WAIT1()  asm volatile("cp.async.wait_group 1;\n")
#define CP_WAIT0()  asm volatile("cp.async.wait_group 0;\n")

#define U(x) __float_as_uint(x)

// ------------------------------------------------------------
// Kernel 0a: decode cluster_ids robustly (int64 vs int32 on disk).
// int64-LE with values 0..7 has words 1,3,...,63 all zero.
// ------------------------------------------------------------
__global__ void decode_cid_kernel(const int* __restrict__ p)
{
    __shared__ int is64;
    if (threadIdx.x == 0) {
        int all0 = 1;
        for (int i = 1; i < 64; i += 2) all0 &= (p[i] == 0);
        is64 = all0;
    }
    __syncthreads();
    int n = threadIdx.x;           // 64 threads
    g_cid[n] = is64 ? p[2 * n] : p[n];
}

// ------------------------------------------------------------
// Kernel 0b: pre-round all weights to tf32. grid 1024x256 covers 262144.
// ------------------------------------------------------------
__global__ void round_weights_kernel(
    const float* __restrict__ Wq, const float* __restrict__ Wv,
    const float* __restrict__ Wk, const float* __restrict__ Pw)
{
    int i = blockIdx.x * blockDim.x + threadIdx.x;   // 0..262143
    g_Wqr[i] = f2tf(Wq[i]);
    g_Wvr[i] = f2tf(Wv[i]);
    g_Pwr[i] = f2tf(Pw[i]);
#pragma unroll
    for (int j = 0; j < 8; j++)
        g_Wkr[j * 262144 + i] = f2tf(Wk[j * 262144 + i]);
}

// ------------------------------------------------------------
// Kernel 1: fused Q/V/K projection, BN=256, cp.async double-buffered.
// grid = (6 col-tiles of 256, 3 t-tiles of 64, 512 bn), 256 threads.
// col tiles 0..1 -> Q, 2..3 -> V (B[n][k] = W rows), 4..5 -> K (B[k][n]).
// Weights come pre-rounded; only A (x) fragments need cvt.
// ------------------------------------------------------------
#define A_STRIDE  36          // 36%32==4 : A frag gathers conflict-free
#define A_STAGE   (64 * A_STRIDE)          // 2304 floats
#define BN_STRIDE 36          // n-major B view
#define BS_STRIDE 264         // k-major B view (K region): 264%32==8
#define B_STAGE   (256 * BN_STRIDE)        // 9216 floats (>= 32*264=8448)
#define GEMM_SMEM_FLOATS (2 * A_STAGE + 2 * B_STAGE)
#define GEMM_SMEM_BYTES  (GEMM_SMEM_FLOATS * 4)       // 92160 B

__global__ __launch_bounds__(256) void qkv_kernel(
    const float* __restrict__ x,
    const float* __restrict__ bq, const float* __restrict__ bv,
    const float* __restrict__ bk)
{
    extern __shared__ float dsm[];
    float* Abase = dsm;                     // 2 stages of [64][36]
    float* Bbase = dsm + 2 * A_STAGE;       // 2 stages of 9216

    const int bn = blockIdx.z;
    const int b  = bn >> 6;
    const int n  = bn & 63;
    const int t0 = blockIdx.y * 64;
    const int j0 = blockIdx.x * 256;
    const int tid  = threadIdx.x;
    const int lane = tid & 31;
    const int warp = tid >> 5;
    const int wm = warp & 1;        // 2 row groups of 32
    const int wn = warp >> 1;       // 4 col groups of 64

    const int region = j0 >> 9;     // 0=Q 1=V 2=K
    const int jloc   = j0 & 511;    // 0 or 256
    const float* W;
    const float* bias;
    if (region == 0)      { W = g_Wqr; bias = bq; }
    else if (region == 1) { W = g_Wvr; bias = bv; }
    else {
        int c = g_cid[n];
        W = g_Wkr + (size_t)c * DD * DD;
        bias = bk + (size_t)c * DD;
    }

    const float* xrow = x + ((size_t)((b * TT + t0) * NN + n)) * DD;

    float acc[2][8][4];
#pragma unroll
    for (int i = 0; i < 2; i++)
#pragma unroll
        for (int j = 0; j < 8; j++)
#pragma unroll
            for (int k = 0; k < 4; k++) acc[i][j][k] = 0.f;

    auto issue = [&](int k0, int st) {
        float* A = Abase + st * A_STAGE;
        float* Bt = Bbase + st * B_STAGE;
#pragma unroll
        for (int i = 0; i < 2; i++) {
            int id = tid + i * 256;
            int r  = id >> 3;
            int c4 = (id & 7) * 4;
            cp_async16(A + r * A_STRIDE + c4,
                       xrow + (size_t)r * NN * DD + k0 + c4);
        }
        if (region < 2) {
#pragma unroll
            for (int i = 0; i < 8; i++) {
                int id = tid + i * 256;
                int nn = id >> 3;
                int k4 = (id & 7) * 4;
                cp_async16(Bt + nn * BN_STRIDE + k4,
                           W + (size_t)(jloc + nn) * DD + k0 + k4);
            }
        } else {
#pragma unroll
            for (int i = 0; i < 8; i++) {
                int id = tid + i * 256;
                int kk = id >> 6;
                int c4 = (id & 63) * 4;
                cp_async16(Bt + kk * BS_STRIDE + c4,
                           W + (size_t)(k0 + kk) * DD + jloc + c4);
            }
        }
        CP_COMMIT();
    };

    issue(0, 0);

    for (int it = 0; it < 16; it++) {
        if (it < 15) issue((it + 1) * 32, (it + 1) & 1);
        if (it < 15) CP_WAIT1(); else CP_WAIT0();
        __syncthreads();

        const float (*As)[A_STRIDE] = (const float(*)[A_STRIDE])(Abase + (it & 1) * A_STAGE);
        const float* Bt = Bbase + (it & 1) * B_STAGE;
        const float (*Bn)[BN_STRIDE] = (const float(*)[BN_STRIDE])Bt;
        const float (*Bs)[BS_STRIDE] = (const float(*)[BS_STRIDE])Bt;

#pragma unroll
        for (int kk = 0; kk < 32; kk += 8) {
            unsigned a[2][4], bf[8][2];
#pragma unroll
            for (int mi = 0; mi < 2; mi++) {
                int r = wm * 32 + mi * 16 + (lane >> 2);
                int c = kk + (lane & 3);
                a[mi][0] = f2tfu(As[r][c]);          // x not pre-rounded
                a[mi][1] = f2tfu(As[r + 8][c]);
                a[mi][2] = f2tfu(As[r][c + 4]);
                a[mi][3] = f2tfu(As[r + 8][c + 4]);
            }
            if (region < 2) {
#pragma unroll
                for (int ni = 0; ni < 8; ni++) {
                    int nc = wn * 64 + ni * 8 + (lane >> 2);
                    int kr = kk + (lane & 3);
                    bf[ni][0] = U(Bn[nc][kr]);       // pre-rounded weights
                    bf[ni][1] = U(Bn[nc][kr + 4]);
                }
            } else {
#pragma unroll
                for (int ni = 0; ni < 8; ni++) {
                    int nc = wn * 64 + ni * 8 + (lane >> 2);
                    int kr = kk + (lane & 3);
                    bf[ni][0] = U(Bs[kr][nc]);
                    bf[ni][1] = U(Bs[kr + 4][nc]);
                }
            }
#pragma unroll
            for (int mi = 0; mi < 2; mi++)
#pragma unroll
                for (int ni = 0; ni < 8; ni++)
                    mma_tf32(acc[mi][ni], a[mi], bf[ni]);
        }
        __syncthreads();
    }

    // epilogue: add bias, round to tf32 (attn consumes as mma operands).
    float* dst = (region == 0) ? g_Q : ((region == 1) ? g_V : g_K);
    const size_t base = (size_t)bn * TOK_PER_BN;
#pragma unroll
    for (int mi = 0; mi < 2; mi++) {
#pragma unroll
        for (int ni = 0; ni < 8; ni++) {
            int r = t0 + wm * 32 + mi * 16 + (lane >> 2);
            int c = jloc + wn * 64 + ni * 8 + 2 * (lane & 3);
            float b0 = bias[c], b1 = bias[c + 1];
            dst[base + (size_t)r * DD + c]           = f2tf(acc[mi][ni][0] + b0);
            dst[base + (size_t)r * DD + c + 1]       = f2tf(acc[mi][ni][1] + b1);
            dst[base + (size_t)(r + 8) * DD + c]     = f2tf(acc[mi][ni][2] + b0);
            dst[base + (size_t)(r + 8) * DD + c + 1] = f2tf(acc[mi][ni][3] + b1);
        }
    }
}

// ------------------------------------------------------------
// Kernel 2: attention per (b,n,h), q-tile of 64 rows.
// grid = (3 q-tiles, 8 heads, 512 bn), 512 threads (16 warps — smem caps
// at 1 block/SM, so more warps is the only occupancy lever), ~171KB smem.
// ------------------------------------------------------------
#define KS_STRIDE 68     // K & Q tiles  (68%32==4 : frag gathers conflict-free)
#define VS_STRIDE 72     // V tile       (72%32==8 : phase-3 B gathers conflict-free)
#define SS_STRIDE 196
#define ATTN_SMEM_FLOATS (192 * KS_STRIDE + 192 * VS_STRIDE + 64 * KS_STRIDE + 64 * SS_STRIDE)
#define ATTN_SMEM_BYTES  (ATTN_SMEM_FLOATS * 4)

__global__ __launch_bounds__(512) void attn_kernel()
{
    extern __shared__ float sm[];
    float (*Ks)[KS_STRIDE] = (float(*)[KS_STRIDE])sm;
    float (*Vs)[VS_STRIDE] = (float(*)[VS_STRIDE])(sm + 192 * KS_STRIDE);
    float (*Qs)[KS_STRIDE] = (float(*)[KS_STRIDE])(sm + 192 * KS_STRIDE + 192 * VS_STRIDE);
    float (*Ss)[SS_STRIDE] = (float(*)[SS_STRIDE])(sm + 192 * KS_STRIDE + 192 * VS_STRIDE + 64 * KS_STRIDE);

    const int bn  = blockIdx.z;
    const int h   = blockIdx.y;
    const int tq0 = blockIdx.x * 64;
    const int tid  = threadIdx.x;
    const int lane = tid & 31;
    const int warp = tid >> 5;      // 0..15
    const int wm = warp & 1;        // 2 row groups of 32
    const int wn = warp >> 1;       // 8 col groups

    const size_t base = (size_t)bn * TOK_PER_BN + (size_t)h * DH;

    // ---- loads: K,V full [192,64]; Q tile [64,64]. Already tf32-rounded.
#pragma unroll
    for (int i = 0; i < 6; i++) {
        int id = tid + i * 512;
        int r  = id >> 4;
        int c4 = (id & 15) * 4;
        *(float4*)&Ks[r][c4] = *(const float4*)(g_K + base + (size_t)r * DD + c4);
        *(float4*)&Vs[r][c4] = *(const float4*)(g_V + base + (size_t)r * DD + c4);
    }
#pragma unroll
    for (int i = 0; i < 2; i++) {
        int id = tid + i * 512;
        int r  = id >> 4;
        int c4 = (id & 15) * 4;
        *(float4*)&Qs[r][c4] = *(const float4*)(g_Q + base + (size_t)(tq0 + r) * DD + c4);
    }
    __syncthreads();

    // ---- phase 1: S = Q K^T  (64x192, k=64); warp tile 32x24
    {
        float acc[2][3][4];
#pragma unroll
        for (int i = 0; i < 2; i++)
#pragma unroll
            for (int j = 0; j < 3; j++)
#pragma unroll
                for (int k = 0; k < 4; k++) acc[i][j][k] = 0.f;

#pragma unroll
        for (int kk = 0; kk < DH; kk += 8) {
            unsigned a[2][4], bf[3][2];
#pragma unroll
            for (int mi = 0; mi < 2; mi++) {
                int r = wm * 32 + mi * 16 + (lane >> 2);
                int c = kk + (lane & 3);
                a[mi][0] = U(Qs[r][c]);
                a[mi][1] = U(Qs[r + 8][c]);
                a[mi][2] = U(Qs[r][c + 4]);
                a[mi][3] = U(Qs[r + 8][c + 4]);
            }
#pragma unroll
            for (int ni = 0; ni < 3; ni++) {
                int nc = wn * 24 + ni * 8 + (lane >> 2);
                int kr = kk + (lane & 3);
                bf[ni][0] = U(Ks[nc][kr]);       // B[k][n] = K[n][k]
                bf[ni][1] = U(Ks[nc][kr + 4]);
            }
#pragma unroll
            for (int mi = 0; mi < 2; mi++)
#pragma unroll
                for (int ni = 0; ni < 3; ni++)
                    mma_tf32(acc[mi][ni], a[mi], bf[ni]);
        }
#pragma unroll
        for (int mi = 0; mi < 2; mi++) {
#pragma unroll
            for (int ni = 0; ni < 3; ni++) {
                int r = wm * 32 + mi * 16 + (lane >> 2);
                int c = wn * 24 + ni * 8 + 2 * (lane & 3);
                Ss[r][c]         = acc[mi][ni][0] * 0.125f;
                Ss[r][c + 1]     = acc[mi][ni][1] * 0.125f;
                Ss[r + 8][c]     = acc[mi][ni][2] * 0.125f;
                Ss[r + 8][c + 1] = acc[mi][ni][3] * 0.125f;
            }
        }
    }
    __syncthreads();

    // ---- phase 2: softmax, 8 threads per row; store P rounded to tf32.
    {
        const int r = tid >> 3;        // 0..63
        const int g = tid & 7;
        float m = -1e30f;
        for (int c = g; c < 192; c += 8) m = fmaxf(m, Ss[r][c]);
        m = fmaxf(m, __shfl_xor_sync(0xFFFFFFFFu, m, 1));
        m = fmaxf(m, __shfl_xor_sync(0xFFFFFFFFu, m, 2));
        m = fmaxf(m, __shfl_xor_sync(0xFFFFFFFFu, m, 4));
        float s = 0.f;
        for (int c = g; c < 192; c += 8) {
            float e = __expf(Ss[r][c] - m);
            Ss[r][c] = e;
            s += e;
        }
        s += __shfl_xor_sync(0xFFFFFFFFu, s, 1);
        s += __shfl_xor_sync(0xFFFFFFFFu, s, 2);
        s += __shfl_xor_sync(0xFFFFFFFFu, s, 4);
        float inv = 1.0f / s;
        for (int c = g; c < 192; c += 8) Ss[r][c] = f2tf(Ss[r][c] * inv);
    }
    __syncthreads();

    // ---- phase 3: O = P V (64x64, k=192); warp tile 32x8
    {
        float acc[2][4];
#pragma unroll
        for (int i = 0; i < 2; i++)
#pragma unroll
            for (int k = 0; k < 4; k++) acc[i][k] = 0.f;

#pragma unroll
        for (int kk = 0; kk < 192; kk += 8) {
            unsigned a[2][4], bf[2];
#pragma unroll
            for (int mi = 0; mi < 2; mi++) {
                int r = wm * 32 + mi * 16 + (lane >> 2);
                int c = kk + (lane & 3);
                a[mi][0] = U(Ss[r][c]);
                a[mi][1] = U(Ss[r + 8][c]);
                a[mi][2] = U(Ss[r][c + 4]);
                a[mi][3] = U(Ss[r + 8][c + 4]);
            }
            {
                int nc = wn * 8 + (lane >> 2);
                int kr = kk + (lane & 3);
                bf[0] = U(Vs[kr][nc]);
                bf[1] = U(Vs[kr + 4][nc]);
            }
#pragma unroll
            for (int mi = 0; mi < 2; mi++)
                mma_tf32(acc[mi], a[mi], bf);
        }

#pragma unroll
        for (int mi = 0; mi < 2; mi++) {
            int r = wm * 32 + mi * 16 + (lane >> 2);
            int c = wn * 8 + 2 * (lane & 3);
            size_t o0 = (size_t)bn * TOK_PER_BN + (size_t)(tq0 + r) * DD + h * DH + c;
            size_t o8 = (size_t)bn * TOK_PER_BN + (size_t)(tq0 + r + 8) * DD + h * DH + c;
            g_O[o0]     = f2tf(acc[mi][0]);
            g_O[o0 + 1] = f2tf(acc[mi][1]);
            g_O[o8]     = f2tf(acc[mi][2]);
            g_O[o8 + 1] = f2tf(acc[mi][3]);
        }
    }
}

// ------------------------------------------------------------
// Kernel 3: output projection, BN=256, cp.async double-buffered.
// out[b,t,n,e] = sum_d O[bn,t,d] * P[e,d] + pb[e]
// grid = (2 col-tiles of 256, 3 t-tiles, 512 bn), 256 threads.
// A (g_O) and B (g_Pwr) both pre-rounded: zero cvts in the hot loop.
// ------------------------------------------------------------
__global__ __launch_bounds__(256) void proj_kernel(
    const float* __restrict__ Pb, float* __restrict__ out)
{
    extern __shared__ float dsm[];
    float* Abase = dsm;
    float* Bbase = dsm + 2 * A_STAGE;

    const int bn = blockIdx.z;
    const int b  = bn >> 6;
    const int n  = bn & 63;
    const int t0 = blockIdx.y * 64;
    const int j0 = blockIdx.x * 256;
    const int tid  = threadIdx.x;
    const int lane = tid & 31;
    const int warp = tid >> 5;
    const int wm = warp & 1;
    const int wn = warp >> 1;

    const float* A = g_O + (size_t)bn * TOK_PER_BN + (size_t)t0 * DD;

    float acc[2][8][4];
#pragma unroll
    for (int i = 0; i < 2; i++)
#pragma unroll
        for (int j = 0; j < 8; j++)
#pragma unroll
            for (int k = 0; k < 4; k++) acc[i][j][k] = 0.f;

    auto issue = [&](int k0, int st) {
        float* Asm = Abase + st * A_STAGE;
        float* Bt  = Bbase + st * B_STAGE;
#pragma unroll
        for (int i = 0; i < 2; i++) {
            int id = tid + i * 256;
            int r  = id >> 3;
            int c4 = (id & 7) * 4;
            cp_async16(Asm + r * A_STRIDE + c4, A + (size_t)r * DD + k0 + c4);
        }
#pragma unroll
        for (int i = 0; i < 8; i++) {
            int id = tid + i * 256;
            int nn = id >> 3;
            int k4 = (id & 7) * 4;
            cp_async16(Bt + nn * BN_STRIDE + k4,
                       g_Pwr + (size_t)(j0 + nn) * DD + k0 + k4);
        }
        CP_COMMIT();
    };

    issue(0, 0);

    for (int it = 0; it < 16; it++) {
        if (it < 15) issue((it + 1) * 32, (it + 1) & 1);
        if (it < 15) CP_WAIT1(); else CP_WAIT0();
        __syncthreads();

        const float (*As)[A_STRIDE] = (const float(*)[A_STRIDE])(Abase + (it & 1) * A_STAGE);
        const float (*Bn)[BN_STRIDE] = (const float(*)[BN_STRIDE])(Bbase + (it & 1) * B_STAGE);

#pragma unroll
        for (int kk = 0; kk < 32; kk += 8) {
            unsigned a[2][4], bf[8][2];
#pragma unroll
            for (int mi = 0; mi < 2; mi++) {
                int r = wm * 32 + mi * 16 + (lane >> 2);
                int c = kk + (lane & 3);
                a[mi][0] = U(As[r][c]);
                a[mi][1] = U(As[r + 8][c]);
                a[mi][2] = U(As[r][c + 4]);
                a[mi][3] = U(As[r + 8][c + 4]);
            }
#pragma unroll
            for (int ni = 0; ni < 8; ni++) {
                int nc = wn * 64 + ni * 8 + (lane >> 2);
                int kr = kk + (lane & 3);
                bf[ni][0] = U(Bn[nc][kr]);
                bf[ni][1] = U(Bn[nc][kr + 4]);
            }
#pragma unroll
            for (int mi = 0; mi < 2; mi++)
#pragma unroll
                for (int ni = 0; ni < 8; ni++)
                    mma_tf32(acc[mi][ni], a[mi], bf[ni]);
        }
        __syncthreads();
    }

#pragma unroll
    for (int mi = 0; mi < 2; mi++) {
#pragma unroll
        for (int ni = 0; ni < 8; ni++) {
            int r = t0 + wm * 32 + mi * 16 + (lane >> 2);
            int c = j0 + wn * 64 + ni * 8 + 2 * (lane & 3);
            float b0 = Pb[c], b1 = Pb[c + 1];
            size_t o0 = ((size_t)(b * TT + r) * NN + n) * DD + c;
            size_t o8 = ((size_t)(b * TT + r + 8) * NN + n) * DD + c;
            out[o0]     = acc[mi][ni][0] + b0;
            out[o0 + 1] = acc[mi][ni][1] + b1;
            out[o8]     = acc[mi][ni][2] + b0;
            out[o8 + 1] = acc[mi][ni][3] + b1;
        }
    }
}

// ------------------------------------------------------------
extern "C" void kernel_launch(void* const* d_in, const int* in_sizes, int n_in,
                              void* d_out, int out_size)
{
    const float* x      = (const float*)d_in[0];
    const float* Wq_w   = (const float*)d_in[1];
    const float* Wq_b   = (const float*)d_in[2];
    const float* Wv_w   = (const float*)d_in[3];
    const float* Wv_b   = (const float*)d_in[4];
    const float* Wk     = (const float*)d_in[5];
    const float* bk     = (const float*)d_in[6];
    const float* proj_w = (const float*)d_in[7];
    const float* proj_b = (const float*)d_in[8];
    const int*   cid    = (const int*)d_in[9];     // int32 or int64 — decoded on device
    float* out = (float*)d_out;

    cudaFuncSetAttribute(qkv_kernel,  cudaFuncAttributeMaxDynamicSharedMemorySize, GEMM_SMEM_BYTES);
    cudaFuncSetAttribute(proj_kernel, cudaFuncAttributeMaxDynamicSharedMemorySize, GEMM_SMEM_BYTES);
    cudaFuncSetAttribute(attn_kernel, cudaFuncAttributeMaxDynamicSharedMemorySize, ATTN_SMEM_BYTES);

    decode_cid_kernel<<<1, 64>>>(cid);
    round_weights_kernel<<<1024, 256>>>(Wq_w, Wv_w, Wk, proj_w);

    dim3 g1(6, 3, 512);
    qkv_kernel<<<g1, 256, GEMM_SMEM_BYTES>>>(x, Wq_b, Wv_b, bk);

    dim3 g2(3, 8, 512);
    attn_kernel<<<g2, 512, ATTN_SMEM_BYTES>>>();

    dim3 g3(2, 3, 512);
    proj_kernel<<<g3, 256, GEMM_SMEM_BYTES>>>(proj_b, out);
}

// round 9
// speedup vs baseline: 1.1645x; 1.1110x over previous
#include <cuda_runtime.h>
#include <cstdint>

// ============================================================
// TemporalSelfAttentionClusterKey  (B=8,T=192,N=64,D=512,H=8,DH=64,C=8)
// tf32 mma.sync (m16n8k8), fp32 accumulate.
// GEMMs: cp.async double-buffered, ldmatrix fragment loads (tf32-via-b16),
// strides == 4 mod 32 (8 ldmatrix rows x 16B tile all 32 banks).
// All weights pre-rounded n-major (Wk transposed at pre-round) -> one
// uniform ldmatrix path in qkv.
// attn: fused register softmax, ph3 fat 32x32 warp tiles.
// ============================================================

#define TT   192
#define DD   512
#define NN   64
#define DH   64

static const size_t TOK_PER_BN = (size_t)TT * DD;      // 98304 floats per (b,n)

__device__ float g_Q[50331648];
__device__ float g_K[50331648];
__device__ float g_V[50331648];
__device__ float g_O[50331648];
__device__ int   g_cid[64];
// tf32-pre-rounded weights (all n-major: W[n][k])
__device__ float g_Wqr[262144];
__device__ float g_Wvr[262144];
__device__ float g_Pwr[262144];
__device__ float g_Wkr[2097152];     // transposed: [c][e][d] = Wk[c][d][e]

__device__ __forceinline__ float f2tf(float x) {
    unsigned r;
    asm("cvt.rna.tf32.f32 %0, %1;" : "=r"(r) : "f"(x));
    return __uint_as_float(r);
}
__device__ __forceinline__ unsigned f2tfu_raw(unsigned xu) {
    unsigned r;
    asm("cvt.rna.tf32.f32 %0, %1;" : "=r"(r) : "f"(__uint_as_float(xu)));
    return r;
}

__device__ __forceinline__ void mma_tf32(float* d, const unsigned* a, const unsigned* b) {
    asm volatile(
        "mma.sync.aligned.m16n8k8.row.col.f32.tf32.tf32.f32 "
        "{%0,%1,%2,%3}, {%4,%5,%6,%7}, {%8,%9}, {%0,%1,%2,%3};\n"
        : "+f"(d[0]), "+f"(d[1]), "+f"(d[2]), "+f"(d[3])
        : "r"(a[0]), "r"(a[1]), "r"(a[2]), "r"(a[3]), "r"(b[0]), "r"(b[1]));
}

// tf32-via-b16 ldmatrix: an 8x4-f32 tile is bit-identical to m8n8-b16
// (16B rows); lane l of each matrix receives f32 element [l>>2][l&3].
__device__ __forceinline__ void ldsm_x4(unsigned& r0, unsigned& r1,
                                        unsigned& r2, unsigned& r3,
                                        const void* p) {
    unsigned a = (unsigned)__cvta_generic_to_shared(p);
    asm volatile("ldmatrix.sync.aligned.m8n8.x4.shared.b16 {%0,%1,%2,%3}, [%4];\n"
                 : "=r"(r0), "=r"(r1), "=r"(r2), "=r"(r3) : "r"(a));
}

__device__ __forceinline__ void cp_async16(void* smem_dst, const void* gmem_src) {
    unsigned s = (unsigned)__cvta_generic_to_shared(smem_dst);
    asm volatile("cp.async.cg.shared.global [%0], [%1], 16;\n" :: "r"(s), "l"(gmem_src));
}
#define CP_COMMIT() asm volatile("cp.async.commit_group;\n")
#define CP_WAIT1()  asm volatile("cp.async.wait_group 1;\n")
#define CP_WAIT0()  asm volatile("cp.async.wait_group 0;\n")

#define U(x) __float_as_uint(x)

// ------------------------------------------------------------
// Kernel 0a: decode cluster_ids (int64 vs int32 on disk).
// ------------------------------------------------------------
__global__ void decode_cid_kernel(const int* __restrict__ p)
{
    __shared__ int is64;
    if (threadIdx.x == 0) {
        int all0 = 1;
        for (int i = 1; i < 64; i += 2) all0 &= (p[i] == 0);
        is64 = all0;
    }
    __syncthreads();
    int n = threadIdx.x;
    g_cid[n] = is64 ? p[2 * n] : p[n];
}

// ------------------------------------------------------------
// Kernel 0b: pre-round Wq/Wv/Pw to tf32 (already n-major).
// ------------------------------------------------------------
__global__ void round_weights_kernel(
    const float* __restrict__ Wq, const float* __restrict__ Wv,
    const float* __restrict__ Pw)
{
    int i = blockIdx.x * blockDim.x + threadIdx.x;
    g_Wqr[i] = f2tf(Wq[i]);
    g_Wvr[i] = f2tf(Wv[i]);
    g_Pwr[i] = f2tf(Pw[i]);
}

// ------------------------------------------------------------
// Kernel 0c: transpose-round Wk: g_Wkr[c][e][d] = tf32(Wk[c][d][e]).
// 32x32 smem tiles; grid (16,16,8), block (32,8).
// ------------------------------------------------------------
__global__ void round_wk_kernel(const float* __restrict__ Wk)
{
    __shared__ float tile[32][33];
    const int c  = blockIdx.z;
    const int d0 = blockIdx.y * 32;
    const int e0 = blockIdx.x * 32;
    const int tx = threadIdx.x;
    const int ty = threadIdx.y;
    const float* src = Wk + (size_t)c * DD * DD;
    float* dst = g_Wkr + (size_t)c * DD * DD;
#pragma unroll
    for (int i = 0; i < 4; i++)
        tile[ty + 8 * i][tx] = f2tf(src[(size_t)(d0 + ty + 8 * i) * DD + e0 + tx]);
    __syncthreads();
#pragma unroll
    for (int i = 0; i < 4; i++)
        dst[(size_t)(e0 + ty + 8 * i) * DD + d0 + tx] = tile[tx][ty + 8 * i];
}

// ------------------------------------------------------------
// GEMM tiling: BM=64, BN=256, BK=32. Strides 36 (== 4 mod 32): ldmatrix
// row offsets land at bank slots 0,4,8,...,28 — all 32 banks, no conflict.
// ------------------------------------------------------------
#define A_STRIDE  36
#define A_STAGE   (64 * A_STRIDE)          // 2304 floats
#define BN_STRIDE 36                        // n-major B view
#define B_STAGE   (256 * BN_STRIDE)        // 9216 floats
#define GEMM_SMEM_FLOATS (2 * A_STAGE + 2 * B_STAGE)
#define GEMM_SMEM_BYTES  (GEMM_SMEM_FLOATS * 4)       // 92160 B

// ------------------------------------------------------------
// Kernel 1: fused Q/V/K projection — uniform n-major ldmatrix path.
// grid = (6 col-tiles of 256, 3 t-tiles of 64, 512 bn), 256 threads.
// ------------------------------------------------------------
__global__ __launch_bounds__(256) void qkv_kernel(
    const float* __restrict__ x,
    const float* __restrict__ bq, const float* __restrict__ bv,
    const float* __restrict__ bk)
{
    extern __shared__ float dsm[];
    float* Abase = dsm;
    float* Bbase = dsm + 2 * A_STAGE;

    const int bn = blockIdx.z;
    const int b  = bn >> 6;
    const int n  = bn & 63;
    const int t0 = blockIdx.y * 64;
    const int j0 = blockIdx.x * 256;
    const int tid  = threadIdx.x;
    const int lane = tid & 31;
    const int warp = tid >> 5;
    const int wm = warp & 1;
    const int wn = warp >> 1;
    const int g  = lane >> 3;
    const int a_radd = (g & 1) ? 8 : 0;   // A: (r,c),(r+8,c),(r,c+4),(r+8,c+4)
    const int a_cadd = (g & 2) ? 4 : 0;
    const int b_radd = (g & 2) ? 8 : 0;   // B: (n,k0),(n,k4),(n+8,k0),(n+8,k4)
    const int b_cadd = (g & 1) ? 4 : 0;
    const int l7 = lane & 7;

    const int region = j0 >> 9;
    const int jloc   = j0 & 511;
    const float* W;
    const float* bias;
    if (region == 0)      { W = g_Wqr; bias = bq; }
    else if (region == 1) { W = g_Wvr; bias = bv; }
    else {
        int c = g_cid[n];
        W = g_Wkr + (size_t)c * DD * DD;   // transposed: n-major
        bias = bk + (size_t)c * DD;
    }

    const float* xrow = x + ((size_t)((b * TT + t0) * NN + n)) * DD;

    float acc[2][8][4];
#pragma unroll
    for (int i = 0; i < 2; i++)
#pragma unroll
        for (int j = 0; j < 8; j++)
#pragma unroll
            for (int k = 0; k < 4; k++) acc[i][j][k] = 0.f;

    auto issue = [&](int k0, int st) {
        float* A = Abase + st * A_STAGE;
        float* Bt = Bbase + st * B_STAGE;
#pragma unroll
        for (int i = 0; i < 2; i++) {
            int id = tid + i * 256;
            int r  = id >> 3;
            int c4 = (id & 7) * 4;
            cp_async16(A + r * A_STRIDE + c4,
                       xrow + (size_t)r * NN * DD + k0 + c4);
        }
#pragma unroll
        for (int i = 0; i < 8; i++) {
            int id = tid + i * 256;
            int nn = id >> 3;
            int k4 = (id & 7) * 4;
            cp_async16(Bt + nn * BN_STRIDE + k4,
                       W + (size_t)(jloc + nn) * DD + k0 + k4);
        }
        CP_COMMIT();
    };

    issue(0, 0);

    for (int it = 0; it < 16; it++) {
        if (it < 15) issue((it + 1) * 32, (it + 1) & 1);
        if (it < 15) CP_WAIT1(); else CP_WAIT0();
        __syncthreads();

        const float* As = Abase + (it & 1) * A_STAGE;
        const float* Bt = Bbase + (it & 1) * B_STAGE;

#pragma unroll
        for (int kk = 0; kk < 32; kk += 8) {
            unsigned a[2][4], bf[8][2];
#pragma unroll
            for (int mi = 0; mi < 2; mi++) {
                int r = wm * 32 + mi * 16 + a_radd + l7;
                ldsm_x4(a[mi][0], a[mi][1], a[mi][2], a[mi][3],
                        As + r * A_STRIDE + kk + a_cadd);
                a[mi][0] = f2tfu_raw(a[mi][0]);      // x not pre-rounded
                a[mi][1] = f2tfu_raw(a[mi][1]);
                a[mi][2] = f2tfu_raw(a[mi][2]);
                a[mi][3] = f2tfu_raw(a[mi][3]);
            }
#pragma unroll
            for (int p = 0; p < 4; p++) {
                int nr = wn * 64 + p * 16 + b_radd + l7;
                ldsm_x4(bf[2 * p][0], bf[2 * p][1],
                        bf[2 * p + 1][0], bf[2 * p + 1][1],
                        Bt + nr * BN_STRIDE + kk + b_cadd);
            }
#pragma unroll
            for (int mi = 0; mi < 2; mi++)
#pragma unroll
                for (int ni = 0; ni < 8; ni++)
                    mma_tf32(acc[mi][ni], a[mi], bf[ni]);
        }
        __syncthreads();
    }

    float* dst = (region == 0) ? g_Q : ((region == 1) ? g_V : g_K);
    const size_t base = (size_t)bn * TOK_PER_BN;
#pragma unroll
    for (int mi = 0; mi < 2; mi++) {
#pragma unroll
        for (int ni = 0; ni < 8; ni++) {
            int r = t0 + wm * 32 + mi * 16 + (lane >> 2);
            int c = jloc + wn * 64 + ni * 8 + 2 * (lane & 3);
            float b0 = bias[c], b1 = bias[c + 1];
            dst[base + (size_t)r * DD + c]           = f2tf(acc[mi][ni][0] + b0);
            dst[base + (size_t)r * DD + c + 1]       = f2tf(acc[mi][ni][1] + b1);
            dst[base + (size_t)(r + 8) * DD + c]     = f2tf(acc[mi][ni][2] + b0);
            dst[base + (size_t)(r + 8) * DD + c + 1] = f2tf(acc[mi][ni][3] + b1);
        }
    }
}

// ------------------------------------------------------------
// Kernel 2: attention per (b,n,h), q-tile 64 rows, 256 threads.
// ph1: 8 warps, 32x48. Fused register softmax. ph3: 4 warps, 32x32.
// ------------------------------------------------------------
#define KS_STRIDE 68     // 68%32==4 : scalar frag gathers conflict-free
#define VS_STRIDE 72     // 72%32==8
#define QS_STRIDE 68
#define SS_STRIDE 196    // 196%32==4 : ph3 A gathers bank==lane
#define OFF_VS  (192 * KS_STRIDE)
#define OFF_QS  (OFF_VS + 192 * VS_STRIDE)
#define OFF_SS  (OFF_QS + 64 * QS_STRIDE)
#define OFF_MB  (OFF_SS + 64 * SS_STRIDE)
#define OFF_SB  (OFF_MB + 64 * 4)
#define ATTN_SMEM_FLOATS (OFF_SB + 64 * 4)
#define ATTN_SMEM_BYTES  (ATTN_SMEM_FLOATS * 4)

__global__ __launch_bounds__(256) void attn_kernel()
{
    extern __shared__ float sm[];
    float (*Ks)[KS_STRIDE] = (float(*)[KS_STRIDE])sm;
    float (*Vs)[VS_STRIDE] = (float(*)[VS_STRIDE])(sm + OFF_VS);
    float (*Qs)[QS_STRIDE] = (float(*)[QS_STRIDE])(sm + OFF_QS);
    float (*Ss)[SS_STRIDE] = (float(*)[SS_STRIDE])(sm + OFF_SS);
    float (*Mbuf)[4] = (float(*)[4])(sm + OFF_MB);
    float (*Sbuf)[4] = (float(*)[4])(sm + OFF_SB);

    const int bn  = blockIdx.z;
    const int h   = blockIdx.y;
    const int tq0 = blockIdx.x * 64;
    const int tid  = threadIdx.x;
    const int lane = tid & 31;
    const int warp = tid >> 5;
    const int wm = warp & 1;
    const int wn = warp >> 1;

    const size_t base = (size_t)bn * TOK_PER_BN + (size_t)h * DH;

#pragma unroll
    for (int i = 0; i < 12; i++) {
        int id = tid + i * 256;
        int r  = id >> 4;
        int c4 = (id & 15) * 4;
        *(float4*)&Ks[r][c4] = *(const float4*)(g_K + base + (size_t)r * DD + c4);
        *(float4*)&Vs[r][c4] = *(const float4*)(g_V + base + (size_t)r * DD + c4);
    }
#pragma unroll
    for (int i = 0; i < 4; i++) {
        int id = tid + i * 256;
        int r  = id >> 4;
        int c4 = (id & 15) * 4;
        *(float4*)&Qs[r][c4] = *(const float4*)(g_Q + base + (size_t)(tq0 + r) * DD + c4);
    }
    __syncthreads();

    // ---- phase 1: S = Q K^T (64x192, k=64); warp tile 32x48
    float acc[2][6][4];
#pragma unroll
    for (int i = 0; i < 2; i++)
#pragma unroll
        for (int j = 0; j < 6; j++)
#pragma unroll
            for (int k = 0; k < 4; k++) acc[i][j][k] = 0.f;

#pragma unroll
    for (int kk = 0; kk < DH; kk += 8) {
        unsigned a[2][4], bf[6][2];
#pragma unroll
        for (int mi = 0; mi < 2; mi++) {
            int r = wm * 32 + mi * 16 + (lane >> 2);
            int c = kk + (lane & 3);
            a[mi][0] = U(Qs[r][c]);
            a[mi][1] = U(Qs[r + 8][c]);
            a[mi][2] = U(Qs[r][c + 4]);
            a[mi][3] = U(Qs[r + 8][c + 4]);
        }
#pragma unroll
        for (int ni = 0; ni < 6; ni++) {
            int nc = wn * 48 + ni * 8 + (lane >> 2);
            int kr = kk + (lane & 3);
            bf[ni][0] = U(Ks[nc][kr]);
            bf[ni][1] = U(Ks[nc][kr + 4]);
        }
#pragma unroll
        for (int mi = 0; mi < 2; mi++)
#pragma unroll
            for (int ni = 0; ni < 6; ni++)
                mma_tf32(acc[mi][ni], a[mi], bf[ni]);
    }

    // ---- fused softmax part 1: scale + in-register row max
    float mx[2][2] = {{-1e30f, -1e30f}, {-1e30f, -1e30f}};
#pragma unroll
    for (int mi = 0; mi < 2; mi++)
#pragma unroll
        for (int ni = 0; ni < 6; ni++) {
#pragma unroll
            for (int k = 0; k < 4; k++) acc[mi][ni][k] *= 0.125f;
            mx[mi][0] = fmaxf(mx[mi][0], fmaxf(acc[mi][ni][0], acc[mi][ni][1]));
            mx[mi][1] = fmaxf(mx[mi][1], fmaxf(acc[mi][ni][2], acc[mi][ni][3]));
        }
#pragma unroll
    for (int mi = 0; mi < 2; mi++)
#pragma unroll
        for (int s = 0; s < 2; s++) {
            mx[mi][s] = fmaxf(mx[mi][s], __shfl_xor_sync(0xFFFFFFFFu, mx[mi][s], 1));
            mx[mi][s] = fmaxf(mx[mi][s], __shfl_xor_sync(0xFFFFFFFFu, mx[mi][s], 2));
        }
    if ((lane & 3) == 0) {
#pragma unroll
        for (int mi = 0; mi < 2; mi++)
#pragma unroll
            for (int s = 0; s < 2; s++)
                Mbuf[wm * 32 + mi * 16 + (lane >> 2) + 8 * s][wn] = mx[mi][s];
    }
    __syncthreads();

    // ---- fused softmax part 2: exp in regs, store tf32(e), partial sums
    float m[2][2], smr[2][2] = {{0.f, 0.f}, {0.f, 0.f}};
#pragma unroll
    for (int mi = 0; mi < 2; mi++)
#pragma unroll
        for (int s = 0; s < 2; s++) {
            float4 v = *(const float4*)&Mbuf[wm * 32 + mi * 16 + (lane >> 2) + 8 * s][0];
            m[mi][s] = fmaxf(fmaxf(v.x, v.y), fmaxf(v.z, v.w));
        }
#pragma unroll
    for (int mi = 0; mi < 2; mi++) {
        int r0 = wm * 32 + mi * 16 + (lane >> 2);
#pragma unroll
        for (int ni = 0; ni < 6; ni++) {
            int c = wn * 48 + ni * 8 + 2 * (lane & 3);
            float e0 = f2tf(__expf(acc[mi][ni][0] - m[mi][0]));
            float e1 = f2tf(__expf(acc[mi][ni][1] - m[mi][0]));
            float e2 = f2tf(__expf(acc[mi][ni][2] - m[mi][1]));
            float e3 = f2tf(__expf(acc[mi][ni][3] - m[mi][1]));
            *(float2*)&Ss[r0][c]     = make_float2(e0, e1);
            *(float2*)&Ss[r0 + 8][c] = make_float2(e2, e3);
            smr[mi][0] += e0 + e1;
            smr[mi][1] += e2 + e3;
        }
    }
#pragma unroll
    for (int mi = 0; mi < 2; mi++)
#pragma unroll
        for (int s = 0; s < 2; s++) {
            smr[mi][s] += __shfl_xor_sync(0xFFFFFFFFu, smr[mi][s], 1);
            smr[mi][s] += __shfl_xor_sync(0xFFFFFFFFu, smr[mi][s], 2);
        }
    if ((lane & 3) == 0) {
#pragma unroll
        for (int mi = 0; mi < 2; mi++)
#pragma unroll
            for (int s = 0; s < 2; s++)
                Sbuf[wm * 32 + mi * 16 + (lane >> 2) + 8 * s][wn] = smr[mi][s];
    }
    __syncthreads();

    // ---- phase 3: O = E V (64x64, k=192); 4 warps, 32x32 tiles
    if (warp < 4) {
        const int wm3 = warp & 1;
        const int wn3 = warp >> 1;
        float acc3[2][4][4];
#pragma unroll
        for (int i = 0; i < 2; i++)
#pragma unroll
            for (int j = 0; j < 4; j++)
#pragma unroll
                for (int k = 0; k < 4; k++) acc3[i][j][k] = 0.f;

#pragma unroll 4
        for (int kk = 0; kk < 192; kk += 8) {
            unsigned a[2][4], bf[4][2];
#pragma unroll
            for (int mi = 0; mi < 2; mi++) {
                int r = wm3 * 32 + mi * 16 + (lane >> 2);
                int c = kk + (lane & 3);
                a[mi][0] = U(Ss[r][c]);
                a[mi][1] = U(Ss[r + 8][c]);
                a[mi][2] = U(Ss[r][c + 4]);
                a[mi][3] = U(Ss[r + 8][c + 4]);
            }
#pragma unroll
            for (int ni = 0; ni < 4; ni++) {
                int nc = wn3 * 32 + ni * 8 + (lane >> 2);
                int kr = kk + (lane & 3);
                bf[ni][0] = U(Vs[kr][nc]);
                bf[ni][1] = U(Vs[kr + 4][nc]);
            }
#pragma unroll
            for (int mi = 0; mi < 2; mi++)
#pragma unroll
                for (int ni = 0; ni < 4; ni++)
                    mma_tf32(acc3[mi][ni], a[mi], bf[ni]);
        }

#pragma unroll
        for (int mi = 0; mi < 2; mi++) {
            int r = wm3 * 32 + mi * 16 + (lane >> 2);
            float4 s0 = *(const float4*)&Sbuf[r][0];
            float4 s1 = *(const float4*)&Sbuf[r + 8][0];
            float inv0 = 1.0f / (s0.x + s0.y + s0.z + s0.w);
            float inv1 = 1.0f / (s1.x + s1.y + s1.z + s1.w);
#pragma unroll
            for (int ni = 0; ni < 4; ni++) {
                int c = wn3 * 32 + ni * 8 + 2 * (lane & 3);
                size_t o0 = (size_t)bn * TOK_PER_BN + (size_t)(tq0 + r) * DD + h * DH + c;
                size_t o8 = o0 + (size_t)8 * DD;
                g_O[o0]     = f2tf(acc3[mi][ni][0] * inv0);
                g_O[o0 + 1] = f2tf(acc3[mi][ni][1] * inv0);
                g_O[o8]     = f2tf(acc3[mi][ni][2] * inv1);
                g_O[o8 + 1] = f2tf(acc3[mi][ni][3] * inv1);
            }
        }
    }
}

// ------------------------------------------------------------
// Kernel 3: output projection. Full ldmatrix, zero cvts in hot loop.
// grid = (2 col-tiles of 256, 3 t-tiles, 512 bn), 256 threads.
// ------------------------------------------------------------
__global__ __launch_bounds__(256) void proj_kernel(
    const float* __restrict__ Pb, float* __restrict__ out)
{
    extern __shared__ float dsm[];
    float* Abase = dsm;
    float* Bbase = dsm + 2 * A_STAGE;

    const int bn = blockIdx.z;
    const int b  = bn >> 6;
    const int n  = bn & 63;
    const int t0 = blockIdx.y * 64;
    const int j0 = blockIdx.x * 256;
    const int tid  = threadIdx.x;
    const int lane = tid & 31;
    const int warp = tid >> 5;
    const int wm = warp & 1;
    const int wn = warp >> 1;
    const int g  = lane >> 3;
    const int a_radd = (g & 1) ? 8 : 0;
    const int a_cadd = (g & 2) ? 4 : 0;
    const int b_radd = (g & 2) ? 8 : 0;
    const int b_cadd = (g & 1) ? 4 : 0;
    const int l7 = lane & 7;

    const float* A = g_O + (size_t)bn * TOK_PER_BN + (size_t)t0 * DD;

    float acc[2][8][4];
#pragma unroll
    for (int i = 0; i < 2; i++)
#pragma unroll
        for (int j = 0; j < 8; j++)
#pragma unroll
            for (int k = 0; k < 4; k++) acc[i][j][k] = 0.f;

    auto issue = [&](int k0, int st) {
        float* Asm = Abase + st * A_STAGE;
        float* Bt  = Bbase + st * B_STAGE;
#pragma unroll
        for (int i = 0; i < 2; i++) {
            int id = tid + i * 256;
            int r  = id >> 3;
            int c4 = (id & 7) * 4;
            cp_async16(Asm + r * A_STRIDE + c4, A + (size_t)r * DD + k0 + c4);
        }
#pragma unroll
        for (int i = 0; i < 8; i++) {
            int id = tid + i * 256;
            int nn = id >> 3;
            int k4 = (id & 7) * 4;
            cp_async16(Bt + nn * BN_STRIDE + k4,
                       g_Pwr + (size_t)(j0 + nn) * DD + k0 + k4);
        }
        CP_COMMIT();
    };

    issue(0, 0);

    for (int it = 0; it < 16; it++) {
        if (it < 15) issue((it + 1) * 32, (it + 1) & 1);
        if (it < 15) CP_WAIT1(); else CP_WAIT0();
        __syncthreads();

        const float* As = Abase + (it & 1) * A_STAGE;
        const float* Bt = Bbase + (it & 1) * B_STAGE;

#pragma unroll
        for (int kk = 0; kk < 32; kk += 8) {
            unsigned a[2][4], bf[8][2];
#pragma unroll
            for (int mi = 0; mi < 2; mi++) {
                int r = wm * 32 + mi * 16 + a_radd + l7;
                ldsm_x4(a[mi][0], a[mi][1], a[mi][2], a[mi][3],
                        As + r * A_STRIDE + kk + a_cadd);
            }
#pragma unroll
            for (int p = 0; p < 4; p++) {
                int nr = wn * 64 + p * 16 + b_radd + l7;
                ldsm_x4(bf[2 * p][0], bf[2 * p][1],
                        bf[2 * p + 1][0], bf[2 * p + 1][1],
                        Bt + nr * BN_STRIDE + kk + b_cadd);
            }
#pragma unroll
            for (int mi = 0; mi < 2; mi++)
#pragma unroll
                for (int ni = 0; ni < 8; ni++)
                    mma_tf32(acc[mi][ni], a[mi], bf[ni]);
        }
        __syncthreads();
    }

#pragma unroll
    for (int mi = 0; mi < 2; mi++) {
#pragma unroll
        for (int ni = 0; ni < 8; ni++) {
            int r = t0 + wm * 32 + mi * 16 + (lane >> 2);
            int c = j0 + wn * 64 + ni * 8 + 2 * (lane & 3);
            float b0 = Pb[c], b1 = Pb[c + 1];
            size_t o0 = ((size_t)(b * TT + r) * NN + n) * DD + c;
            size_t o8 = ((size_t)(b * TT + r + 8) * NN + n) * DD + c;
            out[o0]     = acc[mi][ni][0] + b0;
            out[o0 + 1] = acc[mi][ni][1] + b1;
            out[o8]     = acc[mi][ni][2] + b0;
            out[o8 + 1] = acc[mi][ni][3] + b1;
        }
    }
}

// ------------------------------------------------------------
extern "C" void kernel_launch(void* const* d_in, const int* in_sizes, int n_in,
                              void* d_out, int out_size)
{
    const float* x      = (const float*)d_in[0];
    const float* Wq_w   = (const float*)d_in[1];
    const float* Wq_b   = (const float*)d_in[2];
    const float* Wv_w   = (const float*)d_in[3];
    const float* Wv_b   = (const float*)d_in[4];
    const float* Wk     = (const float*)d_in[5];
    const float* bk     = (const float*)d_in[6];
    const float* proj_w = (const float*)d_in[7];
    const float* proj_b = (const float*)d_in[8];
    const int*   cid    = (const int*)d_in[9];
    float* out = (float*)d_out;

    cudaFuncSetAttribute(qkv_kernel,  cudaFuncAttributeMaxDynamicSharedMemorySize, GEMM_SMEM_BYTES);
    cudaFuncSetAttribute(proj_kernel, cudaFuncAttributeMaxDynamicSharedMemorySize, GEMM_SMEM_BYTES);
    cudaFuncSetAttribute(attn_kernel, cudaFuncAttributeMaxDynamicSharedMemorySize, ATTN_SMEM_BYTES);

    decode_cid_kernel<<<1, 64>>>(cid);
    round_weights_kernel<<<1024, 256>>>(Wq_w, Wv_w, proj_w);
    round_wk_kernel<<<dim3(16, 16, 8), dim3(32, 8)>>>(Wk);

    dim3 g1(6, 3, 512);
    qkv_kernel<<<g1, 256, GEMM_SMEM_BYTES>>>(x, Wq_b, Wv_b, bk);

    dim3 g2(3, 8, 512);
    attn_kernel<<<g2, 256, ATTN_SMEM_BYTES>>>();

    dim3 g3(2, 3, 512);
    proj_kernel<<<g3, 256, GEMM_SMEM_BYTES>>>(proj_b, out);
}